// round 6
// baseline (speedup 1.0000x reference)
#include <cuda_runtime.h>

#define SEQ 100
#define NF  18
#define HD  16
#define TCH 4        // timesteps staged per chunk
#define WPC 4        // warps per CTA (128 threads)
#define BPW 16       // batches per warp (8 per half)
#define XSTR 20      // padded batch stride in xs (bank-conflict relief)

typedef unsigned long long u64;

struct __align__(16) Smem {
    // Pre-duplicated gate weights: [k][j][0]=(wi,wi,wf,wf), [k][j][1]=(wg,wg,wo,wo)
    float4 w1i[NF][HD][2];
    float4 w1h[HD][HD][2];
    float4 w2i[HD][HD][2];
    float4 w2h[HD][HD][2];
    float4 bia1[HD][2];           // duplicated combined bias, same packing
    float4 bia2[HD][2];
    float  xs[WPC][TCH][NF][XSTR];   // batch-packed x, batch contiguous
    float4 h1p[WPC][HD][2][2];    // [j][half][piece]: 8 batch h values (pre-relu)
    float4 h1r[WPC][HD][2][2];    // relu(h1) for layer-2 input
    float4 h2p[WPC][HD][2][2];    // layer-2 h
};

__device__ __forceinline__ u64 ffma2(u64 a, u64 b, u64 c) {
    u64 d;
    asm("fma.rn.f32x2 %0, %1, %2, %3;" : "=l"(d) : "l"(a), "l"(b), "l"(c));
    return d;
}
__device__ __forceinline__ float2 unpk(u64 v) {
    float2 r;
    asm("mov.b64 {%0, %1}, %2;" : "=f"(r.x), "=f"(r.y) : "l"(v));
    return r;
}
__device__ __forceinline__ float sigf(float x) {
    float e = __expf(-x);
    return __fdividef(1.f, 1.f + e);
}
// overflow-safe tanh: tanh(x) = sign(x) * (1 - 2/(exp(2|x|)+1))
__device__ __forceinline__ float tanhfast(float x) {
    float a = fabsf(x);
    float e = __expf(2.f * a);
    float t = 1.f - __fdividef(2.f, e + 1.f);
    return x < 0.f ? -t : t;
}

__global__ void __launch_bounds__(128, 4)
lstm2_kernel(const float* __restrict__ x,
             const float* __restrict__ Wih1, const float* __restrict__ Whh1,
             const float* __restrict__ bih1, const float* __restrict__ bhh1,
             const float* __restrict__ Wih2, const float* __restrict__ Whh2,
             const float* __restrict__ bih2, const float* __restrict__ bhh2,
             float* __restrict__ out)
{
    extern __shared__ Smem sm[];
    Smem& s = sm[0];
    const int tid = threadIdx.x;

    // ---- one-time weight prep: duplicated gate pairs ----
    for (int i = tid; i < NF * HD; i += 128) {
        int k = i / HD, j = i % HD;
        float wi = Wih1[(j     ) * NF + k];
        float wf = Wih1[(16 + j) * NF + k];
        float wg = Wih1[(32 + j) * NF + k];
        float wo = Wih1[(48 + j) * NF + k];
        s.w1i[k][j][0] = make_float4(wi, wi, wf, wf);
        s.w1i[k][j][1] = make_float4(wg, wg, wo, wo);
    }
    for (int i = tid; i < HD * HD; i += 128) {
        int k = i / HD, j = i % HD;
        {
            float wi = Whh1[(j     ) * HD + k];
            float wf = Whh1[(16 + j) * HD + k];
            float wg = Whh1[(32 + j) * HD + k];
            float wo = Whh1[(48 + j) * HD + k];
            s.w1h[k][j][0] = make_float4(wi, wi, wf, wf);
            s.w1h[k][j][1] = make_float4(wg, wg, wo, wo);
        }
        {
            float wi = Wih2[(j     ) * HD + k];
            float wf = Wih2[(16 + j) * HD + k];
            float wg = Wih2[(32 + j) * HD + k];
            float wo = Wih2[(48 + j) * HD + k];
            s.w2i[k][j][0] = make_float4(wi, wi, wf, wf);
            s.w2i[k][j][1] = make_float4(wg, wg, wo, wo);
        }
        {
            float wi = Whh2[(j     ) * HD + k];
            float wf = Whh2[(16 + j) * HD + k];
            float wg = Whh2[(32 + j) * HD + k];
            float wo = Whh2[(48 + j) * HD + k];
            s.w2h[k][j][0] = make_float4(wi, wi, wf, wf);
            s.w2h[k][j][1] = make_float4(wg, wg, wo, wo);
        }
    }
    if (tid < HD) {
        int j = tid;
        float bi = bih1[j] + bhh1[j];
        float bf = bih1[16 + j] + bhh1[16 + j];
        float bg = bih1[32 + j] + bhh1[32 + j];
        float bo = bih1[48 + j] + bhh1[48 + j];
        s.bia1[j][0] = make_float4(bi, bi, bf, bf);
        s.bia1[j][1] = make_float4(bg, bg, bo, bo);
        bi = bih2[j] + bhh2[j];
        bf = bih2[16 + j] + bhh2[16 + j];
        bg = bih2[32 + j] + bhh2[32 + j];
        bo = bih2[48 + j] + bhh2[48 + j];
        s.bia2[j][0] = make_float4(bi, bi, bf, bf);
        s.bia2[j][1] = make_float4(bg, bg, bo, bo);
    }
    __syncthreads();

    const int warp = tid >> 5;
    const int lane = tid & 31;
    const int half = lane >> 4;
    const int j    = lane & 15;
    const int bh   = half * 8;                 // this half's batch offset (0 or 8)
    const long warpBatch = (long)(blockIdx.x * WPC + warp) * BPW;

    // zero h-state
    {
        float4 z = make_float4(0.f, 0.f, 0.f, 0.f);
        s.h1p[warp][j][half][0] = z; s.h1p[warp][j][half][1] = z;
        s.h1r[warp][j][half][0] = z; s.h1r[warp][j][half][1] = z;
        s.h2p[warp][j][half][0] = z; s.h2p[warp][j][half][1] = z;
    }
    float c1[8], c2[8], h2v[8];
#pragma unroll
    for (int b = 0; b < 8; b++) { c1[b] = 0.f; c2[b] = 0.f; h2v[b] = 0.f; }
    __syncwarp();

    const float* xbase = x + warpBatch * (long)(SEQ * NF);

    for (int t = 0; t < SEQ; t++) {
        const int tt = t & (TCH - 1);
        if (tt == 0) {
            // stage TCH steps of x for this warp's 16 batches, batch-packed
            for (int idx = lane; idx < TCH * BPW * NF; idx += 32) {
                int k  = idx % NF;
                int r  = idx / NF;     // tc*16 + b
                int b  = r & 15;
                int tc = r >> 4;
                s.xs[warp][tc][k][b] =
                    xbase[(long)b * (SEQ * NF) + (t + tc) * NF + k];
            }
            __syncwarp();
        }

        // ================= layer 1 =================
        u64 aI[4], aF[4], aG[4], aO[4];
        {
            const u64* bp = (const u64*)&s.bia1[j][0];
            u64 bi = bp[0], bf = bp[1], bg = bp[2], bo = bp[3];
#pragma unroll
            for (int p = 0; p < 4; p++) { aI[p] = bi; aF[p] = bf; aG[p] = bg; aO[p] = bo; }
        }
#pragma unroll
        for (int k = 0; k < NF; k++) {
            const u64* wp = (const u64*)&s.w1i[k][j][0];
            u64 wi = wp[0], wf = wp[1], wg = wp[2], wo = wp[3];
            const u64* xp = (const u64*)&s.xs[warp][tt][k][bh];
            u64 x0 = xp[0], x1 = xp[1], x2 = xp[2], x3 = xp[3];
            aI[0] = ffma2(x0, wi, aI[0]); aF[0] = ffma2(x0, wf, aF[0]);
            aG[0] = ffma2(x0, wg, aG[0]); aO[0] = ffma2(x0, wo, aO[0]);
            aI[1] = ffma2(x1, wi, aI[1]); aF[1] = ffma2(x1, wf, aF[1]);
            aG[1] = ffma2(x1, wg, aG[1]); aO[1] = ffma2(x1, wo, aO[1]);
            aI[2] = ffma2(x2, wi, aI[2]); aF[2] = ffma2(x2, wf, aF[2]);
            aG[2] = ffma2(x2, wg, aG[2]); aO[2] = ffma2(x2, wo, aO[2]);
            aI[3] = ffma2(x3, wi, aI[3]); aF[3] = ffma2(x3, wf, aF[3]);
            aG[3] = ffma2(x3, wg, aG[3]); aO[3] = ffma2(x3, wo, aO[3]);
        }
#pragma unroll
        for (int k = 0; k < HD; k++) {
            const u64* wp = (const u64*)&s.w1h[k][j][0];
            u64 wi = wp[0], wf = wp[1], wg = wp[2], wo = wp[3];
            const u64* hp = (const u64*)&s.h1p[warp][k][half][0];
            u64 h0 = hp[0], h1 = hp[1], h2 = hp[2], h3 = hp[3];
            aI[0] = ffma2(h0, wi, aI[0]); aF[0] = ffma2(h0, wf, aF[0]);
            aG[0] = ffma2(h0, wg, aG[0]); aO[0] = ffma2(h0, wo, aO[0]);
            aI[1] = ffma2(h1, wi, aI[1]); aF[1] = ffma2(h1, wf, aF[1]);
            aG[1] = ffma2(h1, wg, aG[1]); aO[1] = ffma2(h1, wo, aO[1]);
            aI[2] = ffma2(h2, wi, aI[2]); aF[2] = ffma2(h2, wf, aF[2]);
            aG[2] = ffma2(h2, wg, aG[2]); aO[2] = ffma2(h2, wo, aO[2]);
            aI[3] = ffma2(h3, wi, aI[3]); aF[3] = ffma2(h3, wf, aF[3]);
            aG[3] = ffma2(h3, wg, aG[3]); aO[3] = ffma2(h3, wo, aO[3]);
        }
        float h1v[8];
#pragma unroll
        for (int p = 0; p < 4; p++) {
            float2 vi = unpk(aI[p]); float2 vf = unpk(aF[p]);
            float2 vg = unpk(aG[p]); float2 vo = unpk(aO[p]);
            {
                float ig = sigf(vi.x), fg = sigf(vf.x);
                float gg = tanhfast(vg.x), og = sigf(vo.x);
                float c = fmaf(fg, c1[2 * p], ig * gg);
                c1[2 * p] = c;
                h1v[2 * p] = og * tanhfast(c);
            }
            {
                float ig = sigf(vi.y), fg = sigf(vf.y);
                float gg = tanhfast(vg.y), og = sigf(vo.y);
                float c = fmaf(fg, c1[2 * p + 1], ig * gg);
                c1[2 * p + 1] = c;
                h1v[2 * p + 1] = og * tanhfast(c);
            }
        }
        __syncwarp();   // everyone done reading old h1p
        s.h1p[warp][j][half][0] = make_float4(h1v[0], h1v[1], h1v[2], h1v[3]);
        s.h1p[warp][j][half][1] = make_float4(h1v[4], h1v[5], h1v[6], h1v[7]);
        s.h1r[warp][j][half][0] = make_float4(fmaxf(h1v[0], 0.f), fmaxf(h1v[1], 0.f),
                                              fmaxf(h1v[2], 0.f), fmaxf(h1v[3], 0.f));
        s.h1r[warp][j][half][1] = make_float4(fmaxf(h1v[4], 0.f), fmaxf(h1v[5], 0.f),
                                              fmaxf(h1v[6], 0.f), fmaxf(h1v[7], 0.f));
        __syncwarp();   // new h1 visible

        // ================= layer 2 =================
        {
            const u64* bp = (const u64*)&s.bia2[j][0];
            u64 bi = bp[0], bf = bp[1], bg = bp[2], bo = bp[3];
#pragma unroll
            for (int p = 0; p < 4; p++) { aI[p] = bi; aF[p] = bf; aG[p] = bg; aO[p] = bo; }
        }
#pragma unroll
        for (int k = 0; k < HD; k++) {
            const u64* wp = (const u64*)&s.w2i[k][j][0];
            u64 wi = wp[0], wf = wp[1], wg = wp[2], wo = wp[3];
            const u64* hp = (const u64*)&s.h1r[warp][k][half][0];
            u64 h0 = hp[0], h1 = hp[1], h2 = hp[2], h3 = hp[3];
            aI[0] = ffma2(h0, wi, aI[0]); aF[0] = ffma2(h0, wf, aF[0]);
            aG[0] = ffma2(h0, wg, aG[0]); aO[0] = ffma2(h0, wo, aO[0]);
            aI[1] = ffma2(h1, wi, aI[1]); aF[1] = ffma2(h1, wf, aF[1]);
            aG[1] = ffma2(h1, wg, aG[1]); aO[1] = ffma2(h1, wo, aO[1]);
            aI[2] = ffma2(h2, wi, aI[2]); aF[2] = ffma2(h2, wf, aF[2]);
            aG[2] = ffma2(h2, wg, aG[2]); aO[2] = ffma2(h2, wo, aO[2]);
            aI[3] = ffma2(h3, wi, aI[3]); aF[3] = ffma2(h3, wf, aF[3]);
            aG[3] = ffma2(h3, wg, aG[3]); aO[3] = ffma2(h3, wo, aO[3]);
        }
#pragma unroll
        for (int k = 0; k < HD; k++) {
            const u64* wp = (const u64*)&s.w2h[k][j][0];
            u64 wi = wp[0], wf = wp[1], wg = wp[2], wo = wp[3];
            const u64* hp = (const u64*)&s.h2p[warp][k][half][0];
            u64 h0 = hp[0], h1 = hp[1], h2 = hp[2], h3 = hp[3];
            aI[0] = ffma2(h0, wi, aI[0]); aF[0] = ffma2(h0, wf, aF[0]);
            aG[0] = ffma2(h0, wg, aG[0]); aO[0] = ffma2(h0, wo, aO[0]);
            aI[1] = ffma2(h1, wi, aI[1]); aF[1] = ffma2(h1, wf, aF[1]);
            aG[1] = ffma2(h1, wg, aG[1]); aO[1] = ffma2(h1, wo, aO[1]);
            aI[2] = ffma2(h2, wi, aI[2]); aF[2] = ffma2(h2, wf, aF[2]);
            aG[2] = ffma2(h2, wg, aG[2]); aO[2] = ffma2(h2, wo, aO[2]);
            aI[3] = ffma2(h3, wi, aI[3]); aF[3] = ffma2(h3, wf, aF[3]);
            aG[3] = ffma2(h3, wg, aG[3]); aO[3] = ffma2(h3, wo, aO[3]);
        }
#pragma unroll
        for (int p = 0; p < 4; p++) {
            float2 vi = unpk(aI[p]); float2 vf = unpk(aF[p]);
            float2 vg = unpk(aG[p]); float2 vo = unpk(aO[p]);
            {
                float ig = sigf(vi.x), fg = sigf(vf.x);
                float gg = tanhfast(vg.x), og = sigf(vo.x);
                float c = fmaf(fg, c2[2 * p], ig * gg);
                c2[2 * p] = c;
                h2v[2 * p] = og * tanhfast(c);
            }
            {
                float ig = sigf(vi.y), fg = sigf(vf.y);
                float gg = tanhfast(vg.y), og = sigf(vo.y);
                float c = fmaf(fg, c2[2 * p + 1], ig * gg);
                c2[2 * p + 1] = c;
                h2v[2 * p + 1] = og * tanhfast(c);
            }
        }
        __syncwarp();   // everyone done reading old h2p
        s.h2p[warp][j][half][0] = make_float4(h2v[0], h2v[1], h2v[2], h2v[3]);
        s.h2p[warp][j][half][1] = make_float4(h2v[4], h2v[5], h2v[6], h2v[7]);
        __syncwarp();   // new h2 visible
    }

    // ---- output: relu(h2_last), [B, 16] ----
#pragma unroll
    for (int b = 0; b < 8; b++) {
        out[(warpBatch + bh + b) * HD + j] = fmaxf(h2v[b], 0.f);
    }
}

extern "C" void kernel_launch(void* const* d_in, const int* in_sizes, int n_in,
                              void* d_out, int out_size)
{
    const float* x    = (const float*)d_in[0];
    const float* Wih1 = (const float*)d_in[1];
    const float* Whh1 = (const float*)d_in[2];
    const float* bih1 = (const float*)d_in[3];
    const float* bhh1 = (const float*)d_in[4];
    const float* Wih2 = (const float*)d_in[5];
    const float* Whh2 = (const float*)d_in[6];
    const float* bih2 = (const float*)d_in[7];
    const float* bhh2 = (const float*)d_in[8];
    float* out = (float*)d_out;

    const int smem = (int)sizeof(Smem);   // ~70 KB -> needs opt-in
    cudaFuncSetAttribute(lstm2_kernel,
                         cudaFuncAttributeMaxDynamicSharedMemorySize, smem);

    // 16384 batch / (4 warps * 16 batch) = 256 CTAs of 128 threads
    lstm2_kernel<<<256, 128, smem>>>(x, Wih1, Whh1, bih1, bhh1,
                                     Wih2, Whh2, bih2, bhh2, out);
}

// round 7
// speedup vs baseline: 1.2652x; 1.2652x over previous
#include <cuda_runtime.h>

#define SEQ 100
#define NF  18
#define HD  16
#define TCH 2        // timesteps staged per chunk
#define WPC 2        // warps per CTA (64 threads)
#define BPW 8        // batches per warp (4 per half)
#define XSP 10       // padded row stride (float2) for xs
#define HSP 10       // padded row stride (float2) for h arrays

typedef unsigned long long u64;

struct __align__(16) Smem {
    float4 w1i[NF][HD];     // [k][j] = (wi, wf, wg, wo)  gate-packed
    float4 w1h[HD][HD];
    float4 w2i[HD][HD];
    float4 w2h[HD][HD];
    float4 bia1[HD];        // (bi, bf, bg, bo) combined bias
    float4 bia2[HD];
    float2 xs [WPC][TCH][NF][XSP];  // duplicated (v,v), [k][b]
    float2 h1d[WPC][HD][HSP];       // duplicated (h,h), pre-relu (recurrence)
    float2 h1r[WPC][HD][HSP];       // duplicated relu(h) (layer-2 input)
    float2 h2d[WPC][HD][HSP];       // duplicated layer-2 h
};

__device__ __forceinline__ u64 ffma2(u64 a, u64 b, u64 c) {
    u64 d;
    asm("fma.rn.f32x2 %0, %1, %2, %3;" : "=l"(d) : "l"(a), "l"(b), "l"(c));
    return d;
}
__device__ __forceinline__ float2 unpk(u64 v) {
    float2 r;
    asm("mov.b64 {%0, %1}, %2;" : "=f"(r.x), "=f"(r.y) : "l"(v));
    return r;
}
__device__ __forceinline__ float sigf(float x) {
    float e = __expf(-x);
    return __fdividef(1.f, 1.f + e);
}
// overflow-safe tanh: tanh(x) = sign(x) * (1 - 2/(exp(2|x|)+1))
__device__ __forceinline__ float tanhfast(float x) {
    float a = fabsf(x);
    float e = __expf(2.f * a);
    float t = 1.f - __fdividef(2.f, e + 1.f);
    return x < 0.f ? -t : t;
}

// 8 FFMA2: accumulate 4 batches x (i,f) and (g,o) gate pairs for one k
#define KSTEP(WPTR, OPPTR) do {                                          \
    ulonglong2 _w  = *(const ulonglong2*)(WPTR);                         \
    ulonglong2 _oa = *(const ulonglong2*)(OPPTR);                        \
    ulonglong2 _ob = *(const ulonglong2*)((const float2*)(OPPTR) + 2);   \
    aIF0 = ffma2(_oa.x, _w.x, aIF0);  aGO0 = ffma2(_oa.x, _w.y, aGO0);   \
    aIF1 = ffma2(_oa.y, _w.x, aIF1);  aGO1 = ffma2(_oa.y, _w.y, aGO1);   \
    aIF2 = ffma2(_ob.x, _w.x, aIF2);  aGO2 = ffma2(_ob.x, _w.y, aGO2);   \
    aIF3 = ffma2(_ob.y, _w.x, aIF3);  aGO3 = ffma2(_ob.y, _w.y, aGO3);   \
} while (0)

__global__ void __launch_bounds__(64, 8)
lstm2_kernel(const float* __restrict__ x,
             const float* __restrict__ Wih1, const float* __restrict__ Whh1,
             const float* __restrict__ bih1, const float* __restrict__ bhh1,
             const float* __restrict__ Wih2, const float* __restrict__ Whh2,
             const float* __restrict__ bih2, const float* __restrict__ bhh2,
             float* __restrict__ out)
{
    extern __shared__ Smem sm[];
    Smem& s = sm[0];
    const int tid = threadIdx.x;

    // ---- one-time weight prep: gate-packed [k][j] float4 ----
    for (int i = tid; i < NF * HD; i += 64) {
        int k = i >> 4, j = i & 15;
        s.w1i[k][j] = make_float4(Wih1[j * NF + k],        Wih1[(16 + j) * NF + k],
                                  Wih1[(32 + j) * NF + k], Wih1[(48 + j) * NF + k]);
    }
    for (int i = tid; i < HD * HD; i += 64) {
        int k = i >> 4, j = i & 15;
        s.w1h[k][j] = make_float4(Whh1[j * HD + k],        Whh1[(16 + j) * HD + k],
                                  Whh1[(32 + j) * HD + k], Whh1[(48 + j) * HD + k]);
        s.w2i[k][j] = make_float4(Wih2[j * HD + k],        Wih2[(16 + j) * HD + k],
                                  Wih2[(32 + j) * HD + k], Wih2[(48 + j) * HD + k]);
        s.w2h[k][j] = make_float4(Whh2[j * HD + k],        Whh2[(16 + j) * HD + k],
                                  Whh2[(32 + j) * HD + k], Whh2[(48 + j) * HD + k]);
    }
    if (tid < HD) {
        int j = tid;
        s.bia1[j] = make_float4(bih1[j] + bhh1[j],           bih1[16 + j] + bhh1[16 + j],
                                bih1[32 + j] + bhh1[32 + j], bih1[48 + j] + bhh1[48 + j]);
        s.bia2[j] = make_float4(bih2[j] + bhh2[j],           bih2[16 + j] + bhh2[16 + j],
                                bih2[32 + j] + bhh2[32 + j], bih2[48 + j] + bhh2[48 + j]);
    }
    __syncthreads();

    const int warp = tid >> 5;
    const int lane = tid & 31;
    const int half = lane >> 4;
    const int j    = lane & 15;
    const int b0   = half * 4;          // this half's batch offset within warp
    const long warpBatch = (long)(blockIdx.x * WPC + warp) * BPW;
    const float* xbase = x + warpBatch * (long)(SEQ * NF);

    // zero h-state (each thread covers its (j, b0..b0+3))
    {
        float2 z = make_float2(0.f, 0.f);
#pragma unroll
        for (int b = 0; b < 4; b++) {
            s.h1d[warp][j][b0 + b] = z;
            s.h1r[warp][j][b0 + b] = z;
            s.h2d[warp][j][b0 + b] = z;
        }
    }
    float c1[4] = {0.f, 0.f, 0.f, 0.f};
    float c2[4] = {0.f, 0.f, 0.f, 0.f};
    float h2v[4] = {0.f, 0.f, 0.f, 0.f};
    __syncwarp();

    // hoist biases into registers as (bi,bf),(bg,bo) u64 pairs
    const u64* bp1 = (const u64*)&s.bia1[j];
    const u64  b1if = bp1[0], b1go = bp1[1];
    const u64* bp2 = (const u64*)&s.bia2[j];
    const u64  b2if = bp2[0], b2go = bp2[1];

    for (int t = 0; t < SEQ; t++) {
        const int tt = t & (TCH - 1);
        if (tt == 0) {
            __syncwarp();     // previous xs reads complete before overwrite
            // stage TCH steps of x for this warp's 8 batches, duplicated
            for (int idx = lane; idx < TCH * BPW * NF; idx += 32) {
                int k  = idx % NF;
                int r  = idx / NF;        // tc*8 + b
                int b  = r & 7;
                int tc = r >> 3;
                float v = xbase[(long)b * (SEQ * NF) + (t + tc) * NF + k];
                s.xs[warp][tc][k][b] = make_float2(v, v);
            }
            __syncwarp();
        }

        // ================= layer 1 =================
        u64 aIF0 = b1if, aIF1 = b1if, aIF2 = b1if, aIF3 = b1if;
        u64 aGO0 = b1go, aGO1 = b1go, aGO2 = b1go, aGO3 = b1go;
#pragma unroll
        for (int k = 0; k < NF; k++)
            KSTEP(&s.w1i[k][j], &s.xs[warp][tt][k][b0]);
#pragma unroll
        for (int k = 0; k < HD; k++)
            KSTEP(&s.w1h[k][j], &s.h1d[warp][k][b0]);

        float h1v[4];
#pragma unroll
        for (int p = 0; p < 4; p++) {
            u64 aif = (p == 0) ? aIF0 : (p == 1) ? aIF1 : (p == 2) ? aIF2 : aIF3;
            u64 ago = (p == 0) ? aGO0 : (p == 1) ? aGO1 : (p == 2) ? aGO2 : aGO3;
            float2 vif = unpk(aif);
            float2 vgo = unpk(ago);
            float ig = sigf(vif.x), fg = sigf(vif.y);
            float gg = tanhfast(vgo.x), og = sigf(vgo.y);
            float c = fmaf(fg, c1[p], ig * gg);
            c1[p] = c;
            h1v[p] = og * tanhfast(c);
        }
        __syncwarp();   // all lanes done reading old h1d
        {
            float2* hp = &s.h1d[warp][j][b0];
            *(float4*)hp       = make_float4(h1v[0], h1v[0], h1v[1], h1v[1]);
            *(float4*)(hp + 2) = make_float4(h1v[2], h1v[2], h1v[3], h1v[3]);
            float r0 = fmaxf(h1v[0], 0.f), r1 = fmaxf(h1v[1], 0.f);
            float r2 = fmaxf(h1v[2], 0.f), r3 = fmaxf(h1v[3], 0.f);
            float2* rp = &s.h1r[warp][j][b0];
            *(float4*)rp       = make_float4(r0, r0, r1, r1);
            *(float4*)(rp + 2) = make_float4(r2, r2, r3, r3);
        }
        __syncwarp();   // new h1 visible

        // ================= layer 2 =================
        aIF0 = b2if; aIF1 = b2if; aIF2 = b2if; aIF3 = b2if;
        aGO0 = b2go; aGO1 = b2go; aGO2 = b2go; aGO3 = b2go;
#pragma unroll
        for (int k = 0; k < HD; k++)
            KSTEP(&s.w2i[k][j], &s.h1r[warp][k][b0]);
#pragma unroll
        for (int k = 0; k < HD; k++)
            KSTEP(&s.w2h[k][j], &s.h2d[warp][k][b0]);

#pragma unroll
        for (int p = 0; p < 4; p++) {
            u64 aif = (p == 0) ? aIF0 : (p == 1) ? aIF1 : (p == 2) ? aIF2 : aIF3;
            u64 ago = (p == 0) ? aGO0 : (p == 1) ? aGO1 : (p == 2) ? aGO2 : aGO3;
            float2 vif = unpk(aif);
            float2 vgo = unpk(ago);
            float ig = sigf(vif.x), fg = sigf(vif.y);
            float gg = tanhfast(vgo.x), og = sigf(vgo.y);
            float c = fmaf(fg, c2[p], ig * gg);
            c2[p] = c;
            h2v[p] = og * tanhfast(c);
        }
        __syncwarp();   // all lanes done reading old h2d
        {
            float2* hp = &s.h2d[warp][j][b0];
            *(float4*)hp       = make_float4(h2v[0], h2v[0], h2v[1], h2v[1]);
            *(float4*)(hp + 2) = make_float4(h2v[2], h2v[2], h2v[3], h2v[3]);
        }
        __syncwarp();   // new h2 visible
    }

    // ---- output: relu(h2_last), [B, 16] ----
#pragma unroll
    for (int p = 0; p < 4; p++) {
        out[(warpBatch + b0 + p) * HD + j] = fmaxf(h2v[p], 0.f);
    }
}

extern "C" void kernel_launch(void* const* d_in, const int* in_sizes, int n_in,
                              void* d_out, int out_size)
{
    const float* x    = (const float*)d_in[0];
    const float* Wih1 = (const float*)d_in[1];
    const float* Whh1 = (const float*)d_in[2];
    const float* bih1 = (const float*)d_in[3];
    const float* bhh1 = (const float*)d_in[4];
    const float* Wih2 = (const float*)d_in[5];
    const float* Whh2 = (const float*)d_in[6];
    const float* bih2 = (const float*)d_in[7];
    const float* bhh2 = (const float*)d_in[8];
    float* out = (float*)d_out;

    const int smem = (int)sizeof(Smem);   // ~30.1 KB
    cudaFuncSetAttribute(lstm2_kernel,
                         cudaFuncAttributeMaxDynamicSharedMemorySize, smem);

    // 16384 batch / (2 warps * 8 batch) = 1024 CTAs of 64 threads
    // 1024/148 = 6.92 CTAs/SM -> near-perfect load balance, 14 warps/SM
    lstm2_kernel<<<1024, 64, smem>>>(x, Wih1, Whh1, bih1, bhh1,
                                     Wih2, Whh2, bih2, bhh2, out);
}

// round 9
// speedup vs baseline: 1.2818x; 1.0131x over previous
#include <cuda_runtime.h>

#define SEQ 100
#define NF  18
#define HD  16
#define TCH 2        // timesteps staged per chunk
#define WPC 2        // warps per CTA (64 threads)
#define BPW 8        // batches per warp (4 per half)
#define XSP 10       // padded row stride (float2) -> 80B rows, 16B-aligned
#define HSP 10       // padded row stride (float2) -> 80B rows, 16B-aligned

typedef unsigned long long u64;

struct __align__(16) Smem {
    float4 w1i[NF][HD];     // [k][j] = (wi, wf, wg, wo)  gate-packed
    float4 w1h[HD][HD];
    float4 w2i[HD][HD];
    float4 w2h[HD][HD];
    float4 bia1[HD];        // (bi, bf, bg, bo) combined bias
    float4 bia2[HD];
    float2 xs [WPC][TCH][NF][XSP];  // duplicated (v,v), [k][b]
    float2 h1d[WPC][HD][HSP];       // duplicated (h,h), pre-relu (recurrence)
    float2 h1r[WPC][HD][HSP];       // duplicated relu(h) (layer-2 input)
    float2 h2d[WPC][HD][HSP];       // duplicated layer-2 h
};

__device__ __forceinline__ u64 ffma2(u64 a, u64 b, u64 c) {
    u64 d;
    asm("fma.rn.f32x2 %0, %1, %2, %3;" : "=l"(d) : "l"(a), "l"(b), "l"(c));
    return d;
}
__device__ __forceinline__ float2 unpk(u64 v) {
    float2 r;
    asm("mov.b64 {%0, %1}, %2;" : "=f"(r.x), "=f"(r.y) : "l"(v));
    return r;
}
__device__ __forceinline__ float sigf(float x) {
    float e = __expf(-x);
    return __fdividef(1.f, 1.f + e);
}
// overflow-safe tanh: tanh(x) = sign(x) * (1 - 2/(exp(2|x|)+1))
__device__ __forceinline__ float tanhfast(float x) {
    float a = fabsf(x);
    float e = __expf(2.f * a);
    float t = 1.f - __fdividef(2.f, e + 1.f);
    return x < 0.f ? -t : t;
}

// 8 FFMA2 on a named accumulator set: 4 batches x (i,f),(g,o) gate pairs, one k
#define KSTEP(AI0,AG0,AI1,AG1,AI2,AG2,AI3,AG3, WPTR, OPPTR) do {        \
    ulonglong2 _w  = *(const ulonglong2*)(WPTR);                        \
    ulonglong2 _oa = *(const ulonglong2*)(OPPTR);                       \
    ulonglong2 _ob = *(const ulonglong2*)((const float2*)(OPPTR) + 2);  \
    AI0 = ffma2(_oa.x, _w.x, AI0);  AG0 = ffma2(_oa.x, _w.y, AG0);      \
    AI1 = ffma2(_oa.y, _w.x, AI1);  AG1 = ffma2(_oa.y, _w.y, AG1);      \
    AI2 = ffma2(_ob.x, _w.x, AI2);  AG2 = ffma2(_ob.x, _w.y, AG2);      \
    AI3 = ffma2(_ob.y, _w.x, AI3);  AG3 = ffma2(_ob.y, _w.y, AG3);      \
} while (0)

__global__ void __launch_bounds__(64, 7)
lstm2_kernel(const float* __restrict__ x,
             const float* __restrict__ Wih1, const float* __restrict__ Whh1,
             const float* __restrict__ bih1, const float* __restrict__ bhh1,
             const float* __restrict__ Wih2, const float* __restrict__ Whh2,
             const float* __restrict__ bih2, const float* __restrict__ bhh2,
             float* __restrict__ out)
{
    extern __shared__ Smem sm[];
    Smem& s = sm[0];
    const int tid = threadIdx.x;

    // ---- one-time weight prep: gate-packed [k][j] float4 ----
    for (int i = tid; i < NF * HD; i += 64) {
        int k = i >> 4, j = i & 15;
        s.w1i[k][j] = make_float4(Wih1[j * NF + k],        Wih1[(16 + j) * NF + k],
                                  Wih1[(32 + j) * NF + k], Wih1[(48 + j) * NF + k]);
    }
    for (int i = tid; i < HD * HD; i += 64) {
        int k = i >> 4, j = i & 15;
        s.w1h[k][j] = make_float4(Whh1[j * HD + k],        Whh1[(16 + j) * HD + k],
                                  Whh1[(32 + j) * HD + k], Whh1[(48 + j) * HD + k]);
        s.w2i[k][j] = make_float4(Wih2[j * HD + k],        Wih2[(16 + j) * HD + k],
                                  Wih2[(32 + j) * HD + k], Wih2[(48 + j) * HD + k]);
        s.w2h[k][j] = make_float4(Whh2[j * HD + k],        Whh2[(16 + j) * HD + k],
                                  Whh2[(32 + j) * HD + k], Whh2[(48 + j) * HD + k]);
    }
    if (tid < HD) {
        int j = tid;
        s.bia1[j] = make_float4(bih1[j] + bhh1[j],           bih1[16 + j] + bhh1[16 + j],
                                bih1[32 + j] + bhh1[32 + j], bih1[48 + j] + bhh1[48 + j]);
        s.bia2[j] = make_float4(bih2[j] + bhh2[j],           bih2[16 + j] + bhh2[16 + j],
                                bih2[32 + j] + bhh2[32 + j], bih2[48 + j] + bhh2[48 + j]);
    }
    __syncthreads();

    const int warp = tid >> 5;
    const int lane = tid & 31;
    const int half = lane >> 4;
    const int j    = lane & 15;
    const int b0   = half * 4;          // this half's batch offset within warp
    const long warpBatch = (long)(blockIdx.x * WPC + warp) * BPW;
    const float* xbase = x + warpBatch * (long)(SEQ * NF);

    // zero h-state
    {
        float2 z = make_float2(0.f, 0.f);
#pragma unroll
        for (int b = 0; b < 4; b++) {
            s.h1d[warp][j][b0 + b] = z;
            s.h1r[warp][j][b0 + b] = z;
            s.h2d[warp][j][b0 + b] = z;
        }
    }
    float c1[4] = {0.f, 0.f, 0.f, 0.f};
    float c2[4] = {0.f, 0.f, 0.f, 0.f};
    float h2v[4] = {0.f, 0.f, 0.f, 0.f};
    __syncwarp();

    // hoist biases into registers as (bi,bf),(bg,bo) u64 pairs
    const u64* bp1 = (const u64*)&s.bia1[j];
    const u64  b1if = bp1[0], b1go = bp1[1];
    const u64* bp2 = (const u64*)&s.bia2[j];
    const u64  b2if = bp2[0], b2go = bp2[1];

    for (int t = 0; t < SEQ; t++) {
        const int tt = t & (TCH - 1);
        if (tt == 0) {
            __syncwarp();     // previous xs reads complete before overwrite
            // stage TCH steps of x for this warp's 8 batches, duplicated
            for (int idx = lane; idx < TCH * BPW * NF; idx += 32) {
                int k  = idx % NF;
                int r  = idx / NF;        // tc*8 + b
                int b  = r & 7;
                int tc = r >> 3;
                float v = xbase[(long)b * (SEQ * NF) + (t + tc) * NF + k];
                s.xs[warp][tc][k][b] = make_float2(v, v);
            }
            __syncwarp();
        }

        // ====== merged barrier-free matvec region (50 k-steps, 2 acc sets) ======
        // layer-1 full matvec + layer-2 recurrent (W_hh2 * h2(t-1)) part
        u64 aIF0 = b1if, aIF1 = b1if, aIF2 = b1if, aIF3 = b1if;
        u64 aGO0 = b1go, aGO1 = b1go, aGO2 = b1go, aGO3 = b1go;
        u64 bIF0 = b2if, bIF1 = b2if, bIF2 = b2if, bIF3 = b2if;
        u64 bGO0 = b2go, bGO1 = b2go, bGO2 = b2go, bGO3 = b2go;

#pragma unroll
        for (int k = 0; k < NF; k++)
            KSTEP(aIF0,aGO0,aIF1,aGO1,aIF2,aGO2,aIF3,aGO3,
                  &s.w1i[k][j], &s.xs[warp][tt][k][b0]);
#pragma unroll
        for (int k = 0; k < HD; k++) {
            KSTEP(aIF0,aGO0,aIF1,aGO1,aIF2,aGO2,aIF3,aGO3,
                  &s.w1h[k][j], &s.h1d[warp][k][b0]);
            KSTEP(bIF0,bGO0,bIF1,bGO1,bIF2,bGO2,bIF3,bGO3,
                  &s.w2h[k][j], &s.h2d[warp][k][b0]);
        }

        // ---- layer-1 activations ----
        float h1v[4];
#pragma unroll
        for (int p = 0; p < 4; p++) {
            u64 aif = (p == 0) ? aIF0 : (p == 1) ? aIF1 : (p == 2) ? aIF2 : aIF3;
            u64 ago = (p == 0) ? aGO0 : (p == 1) ? aGO1 : (p == 2) ? aGO2 : aGO3;
            float2 vif = unpk(aif);
            float2 vgo = unpk(ago);
            float ig = sigf(vif.x), fg = sigf(vif.y);
            float gg = tanhfast(vgo.x), og = sigf(vgo.y);
            float c = fmaf(fg, c1[p], ig * gg);
            c1[p] = c;
            h1v[p] = og * tanhfast(c);
        }
        __syncwarp();   // all lanes done reading old h1d (and old h2d)
        {
            float2* hp = &s.h1d[warp][j][b0];
            *(float4*)hp       = make_float4(h1v[0], h1v[0], h1v[1], h1v[1]);
            *(float4*)(hp + 2) = make_float4(h1v[2], h1v[2], h1v[3], h1v[3]);
            float r0 = fmaxf(h1v[0], 0.f), r1 = fmaxf(h1v[1], 0.f);
            float r2 = fmaxf(h1v[2], 0.f), r3 = fmaxf(h1v[3], 0.f);
            float2* rp = &s.h1r[warp][j][b0];
            *(float4*)rp       = make_float4(r0, r0, r1, r1);
            *(float4*)(rp + 2) = make_float4(r2, r2, r3, r3);
        }
        __syncwarp();   // new h1 visible

        // ====== layer-2 input part (W_ih2 * relu(h1(t))) ======
#pragma unroll
        for (int k = 0; k < HD; k++)
            KSTEP(bIF0,bGO0,bIF1,bGO1,bIF2,bGO2,bIF3,bGO3,
                  &s.w2i[k][j], &s.h1r[warp][k][b0]);

#pragma unroll
        for (int p = 0; p < 4; p++) {
            u64 aif = (p == 0) ? bIF0 : (p == 1) ? bIF1 : (p == 2) ? bIF2 : bIF3;
            u64 ago = (p == 0) ? bGO0 : (p == 1) ? bGO1 : (p == 2) ? bGO2 : bGO3;
            float2 vif = unpk(aif);
            float2 vgo = unpk(ago);
            float ig = sigf(vif.x), fg = sigf(vif.y);
            float gg = tanhfast(vgo.x), og = sigf(vgo.y);
            float c = fmaf(fg, c2[p], ig * gg);
            c2[p] = c;
            h2v[p] = og * tanhfast(c);
        }
        __syncwarp();   // all lanes done reading old h2d (in merged region)
        {
            float2* hp = &s.h2d[warp][j][b0];
            *(float4*)hp       = make_float4(h2v[0], h2v[0], h2v[1], h2v[1]);
            *(float4*)(hp + 2) = make_float4(h2v[2], h2v[2], h2v[3], h2v[3]);
        }
        __syncwarp();   // new h2 visible
    }

    // ---- output: relu(h2_last), [B, 16] ----
#pragma unroll
    for (int p = 0; p < 4; p++) {
        out[(warpBatch + b0 + p) * HD + j] = fmaxf(h2v[p], 0.f);
    }
}

extern "C" void kernel_launch(void* const* d_in, const int* in_sizes, int n_in,
                              void* d_out, int out_size)
{
    const float* x    = (const float*)d_in[0];
    const float* Wih1 = (const float*)d_in[1];
    const float* Whh1 = (const float*)d_in[2];
    const float* bih1 = (const float*)d_in[3];
    const float* bhh1 = (const float*)d_in[4];
    const float* Wih2 = (const float*)d_in[5];
    const float* Whh2 = (const float*)d_in[6];
    const float* bih2 = (const float*)d_in[7];
    const float* bhh2 = (const float*)d_in[8];
    float* out = (float*)d_out;

    const int smem = (int)sizeof(Smem);   // ~30.1 KB -> 7 CTAs/SM
    cudaFuncSetAttribute(lstm2_kernel,
                         cudaFuncAttributeMaxDynamicSharedMemorySize, smem);

    // 16384 batch / (2 warps * 8 batch) = 1024 CTAs of 64 threads
    lstm2_kernel<<<1024, 64, smem>>>(x, Wih1, Whh1, bih1, bhh1,
                                     Wih2, Whh2, bih2, bhh2, out);
}